// round 11
// baseline (speedup 1.0000x reference)
#include <cuda_runtime.h>

// 3-level Haar DWT, fully fused, 16 inputs per thread.
// x: [B, L=16384] fp32. Output concat: [cA3 (B*2048) | cD3 (B*2048) | cD2 (B*4096) | cD1 (B*8192)]
//
// One thread handles 16 consecutive input samples (two cA3/cD3 groups):
//   loads : 4x LDG.128 (64B contiguous per thread, MLP=4)
//   stores: cD1 2x STG.128, cD2 1x STG.128, cD3 STG.64, cA3 STG.64 — all coalesced.
// Streaming hints (.cs) on everything: zero temporal reuse.

__global__ __launch_bounds__(256) void haar3_kernel16(
    const float4* __restrict__ in4,   // input as float4
    float2* __restrict__ cA3_2,       // B*2048 floats = B*1024 float2
    float2* __restrict__ cD3_2,       // B*2048 floats = B*1024 float2
    float4* __restrict__ cD2_4,       // B*4096 floats = B*1024 float4
    float4* __restrict__ cD1_4,       // B*8192 floats = B*2048 float4
    int total)                        // B * 1024
{
    int t = blockIdx.x * blockDim.x + threadIdx.x;
    if (t >= total) return;

    // thread reads input float4s [4t .. 4t+3]  (64 bytes contiguous)
    float4 v0 = __ldcs(&in4[4 * t + 0]);
    float4 v1 = __ldcs(&in4[4 * t + 1]);
    float4 v2 = __ldcs(&in4[4 * t + 2]);
    float4 v3 = __ldcs(&in4[4 * t + 3]);

    const float S  = 0.70710678118654752440f;   // 2^-1/2
    const float S2 = 0.5f;                      // S^2
    const float S3 = 0.35355339059327376220f;   // S^3

    // ---- level 1: 8 pair sums/diffs ----
    float a0 = v0.x + v0.y, d0 = v0.x - v0.y;
    float a1 = v0.z + v0.w, d1 = v0.z - v0.w;
    float a2 = v1.x + v1.y, d2 = v1.x - v1.y;
    float a3 = v1.z + v1.w, d3 = v1.z - v1.w;
    float a4 = v2.x + v2.y, d4 = v2.x - v2.y;
    float a5 = v2.z + v2.w, d5 = v2.z - v2.w;
    float a6 = v3.x + v3.y, d6 = v3.x - v3.y;
    float a7 = v3.z + v3.w, d7 = v3.z - v3.w;

    // ---- level 2: 4 sums/diffs ----
    float A0 = a0 + a1, D0 = a0 - a1;
    float A1 = a2 + a3, D1 = a2 - a3;
    float A2 = a4 + a5, D2 = a4 - a5;
    float A3 = a6 + a7, D3 = a6 - a7;

    // ---- level 3: 2 sums/diffs ----
    float ca0 = S3 * (A0 + A1), cd0 = S3 * (A0 - A1);
    float ca1 = S3 * (A2 + A3), cd1 = S3 * (A2 - A3);

    // ---- stores (all streaming, all coalesced) ----
    __stcs(&cD1_4[2 * t + 0], make_float4(S * d0, S * d1, S * d2, S * d3));
    __stcs(&cD1_4[2 * t + 1], make_float4(S * d4, S * d5, S * d6, S * d7));
    __stcs(&cD2_4[t], make_float4(S2 * D0, S2 * D1, S2 * D2, S2 * D3));
    __stcs(&cD3_2[t], make_float2(cd0, cd1));
    __stcs(&cA3_2[t], make_float2(ca0, ca1));
}

extern "C" void kernel_launch(void* const* d_in, const int* in_sizes, int n_in,
                              void* d_out, int out_size)
{
    const float* x = (const float*)d_in[0];
    float* out = (float*)d_out;

    const int L = 16384;
    const int B = in_sizes[0] / L;          // 2048
    const int total = B * (L / 16);         // B * 1024 threads

    // Output layout: [cA3 | cD3 | cD2 | cD1]
    float2* cA3 = (float2*)out;
    float2* cD3 = (float2*)(out + (size_t)B * (L / 8));       // + B*2048
    float4* cD2 = (float4*)(out + (size_t)2 * B * (L / 8));   // + B*4096
    float4* cD1 = (float4*)(out + (size_t)B * (L / 2));       // + B*8192

    int threads = 256;
    int blocks = (total + threads - 1) / threads;
    haar3_kernel16<<<blocks, threads>>>((const float4*)x, cA3, cD3, cD2, cD1, total);
}